// round 8
// baseline (speedup 1.0000x reference)
#include <cuda_runtime.h>
#include <cuda_bf16.h>
#include <cstdint>

// Problem dims (fixed by the reference)
#define VOCAB 50000
#define EDIM  64
#define HDIM  64
#define BATCH 1024
#define SEQ   512
#define CHUNK 32
#define NCHUNK (SEQ / CHUNK)

// Scratch: projected table proj[v][h] = b_ih[h]+b_hh[h] + sum_e emb[v,e]*W_ih[h,e]
__device__ float g_proj[VOCAB * HDIM];   // 12.8 MB, L2-resident in steady state
__device__ int   g_x64flag;              // 1 if token buffer is int64, 0 if int32

// Fast tanh: tanh(x) = 1 - 2/(1 + exp(2x)). ex2.approx + rcp.approx,
// rel err ~1e-6 (vs ~6e-4 for tanh.approx.f32, which would risk the 1e-3 gate).
__device__ __forceinline__ float fast_tanh(float x) {
    float e, r;
    asm("ex2.approx.f32 %0, %1;" : "=f"(e) : "f"(x * 2.885390081777927f)); // 2/ln2
    asm("rcp.approx.f32 %0, %1;" : "=f"(r) : "f"(e + 1.0f));
    return fmaf(-2.0f, r, 1.0f);
}

#define FMA2(acc, a, b) asm("fma.rn.f32x2 %0, %1, %2, %0;" : "+l"(acc) : "l"(a), "l"(b))
#define ADD2(acc, b)    asm("add.rn.f32x2 %0, %0, %1;"     : "+l"(acc) : "l"(b))

__device__ __forceinline__ uint32_t smem_u32(const void* p) {
    uint32_t a;
    asm("{ .reg .u64 t; cvta.to.shared.u64 t, %1; cvt.u32.u64 %0, t; }" : "=r"(a) : "l"(p));
    return a;
}
#define CP_ASYNC16(dst_u32, src_ptr) \
    asm volatile("cp.async.cg.shared.global [%0], [%1], 16;" :: "r"(dst_u32), "l"(src_ptr))
#define CP_COMMIT() asm volatile("cp.async.commit_group;" ::: "memory")
#define CP_WAIT0()  asm volatile("cp.async.wait_group 0;"  ::: "memory")

// ---------------------------------------------------------------------------
// Kernel A: build projected embedding table (fuses gather-side GEMM + biases).
// Block 0 warp 0 additionally detects int32-vs-int64 token layout: tokens are
// in [0,50000), so for little-endian int64 every odd 32-bit word is 0.
// ---------------------------------------------------------------------------
#define PROJ_ROWS 32
__global__ __launch_bounds__(256) void proj_kernel(
    const int*   __restrict__ x32,
    const float* __restrict__ emb,
    const float* __restrict__ W_ih,
    const float* __restrict__ b_ih,
    const float* __restrict__ b_hh)
{
    __shared__ float s_w[HDIM * 65];
    __shared__ float s_e[PROJ_ROWS * EDIM];
    __shared__ float s_bias[HDIM];

    const int t  = threadIdx.x;
    const int v0 = blockIdx.x * PROJ_ROWS;

    if (blockIdx.x == 0 && t < 32) {
        unsigned m = __ballot_sync(0xffffffff, x32[2 * t + 1] != 0);
        if (t == 0) g_x64flag = (m == 0u) ? 1 : 0;
    }

    #pragma unroll
    for (int k = 0; k < 16; k++) {
        int idx = t + k * 256;                 // 0..4095
        int hg = idx >> 6, eg = idx & 63;
        s_w[hg * 65 + eg] = W_ih[idx];
    }
    #pragma unroll
    for (int k = 0; k < 8; k++) {
        int idx = t + k * 256;                 // 0..2047
        int r = idx >> 6, e = idx & 63;
        s_e[idx] = (v0 + r < VOCAB) ? emb[(long)(v0 + r) * EDIM + e] : 0.0f;
    }
    if (t < HDIM) s_bias[t] = b_ih[t] + b_hh[t];
    __syncthreads();

    const int h    = t & 63;
    const int rgrp = t >> 6;                   // 0..3
    #pragma unroll
    for (int k = 0; k < 8; k++) {
        int r = rgrp + 4 * k;                  // 0..31
        if (v0 + r >= VOCAB) break;
        float acc = s_bias[h];
        #pragma unroll
        for (int e = 0; e < EDIM; e++)
            acc += s_e[r * EDIM + e] * s_w[h * 65 + e];
        g_proj[(v0 + r) * HDIM + h] = acc;
    }
}

// ---------------------------------------------------------------------------
// Kernel B: ONE row per 64-thread block (2048 warps total -> ~3.5/SMSP).
// Thread i owns output h[i]; weights W_hh[i][:] as 32 j-pair-packed regs
// (direct LDG.128, no duplication -> no spill). Accumulator lanes hold
// (even-j, odd-j) partial sums. One __syncthreads per step (read cur /
// write nxt / bar is race-free). xp staged per 32-step chunk via cp.async,
// 1 copy/thread spread over the chunk's first 16 steps (every other step).
// ---------------------------------------------------------------------------
__global__ __launch_bounds__(64, 7) void rnn_row_kernel(
    const int*   __restrict__ x32,
    const float* __restrict__ W_hh,
    const float* __restrict__ fc_w,
    const float* __restrict__ fc_b,
    float*       __restrict__ out)
{
    __shared__ int    s_tok[SEQ];              // 2 KB
    __shared__ float  s_h[2][HDIM];            // 512 B
    __shared__ float  s_xp[2][CHUNK * HDIM];   // 16 KB
    __shared__ float2 s_part[2];

    const int i   = threadIdx.x;
    const int row = blockIdx.x;
    const int flag = g_x64flag;

    // Tokens for this row (handles int32 or int64 source layout)
    for (int k = i; k < SEQ; k += 64) {
        long base = (long)row * SEQ + k;
        s_tok[k] = flag ? x32[2 * base] : x32[base];
    }

    // W_hh row i packed over j-pairs: 32 x 64-bit regs, natural 128-bit loads
    unsigned long long wp[HDIM / 2];
    {
        const ulonglong2* wv = (const ulonglong2*)(W_hh + i * HDIM);
        #pragma unroll
        for (int q = 0; q < 16; q++) {
            ulonglong2 u = wv[q];
            wp[2 * q + 0] = u.x;
            wp[2 * q + 1] = u.y;
        }
    }

    s_h[0][i] = 0.0f;
    __syncthreads();   // tokens visible to all 64 threads before staging

    // Stage chunk 0: 512 16B-copies, 8 per thread.
    #pragma unroll
    for (int m = 0; m < 8; m++) {
        int id = i + 64 * m;                  // 0..511
        int st = id >> 4, gp = id & 15;
        CP_ASYNC16(smem_u32(&s_xp[0][st * HDIM + gp * 4]),
                   g_proj + s_tok[st] * HDIM + gp * 4);
    }
    CP_COMMIT(); CP_WAIT0();
    __syncthreads();

    float hv = 0.0f;

    #pragma unroll 1
    for (int c = 0; c < NCHUNK; c++) {
        const int xbuf = c & 1;
        const bool more = (c + 1 < NCHUNK);

        #pragma unroll 2
        for (int s = 0; s < CHUNK; s++) {
            // Spread next-chunk prefetch: 1 copy/thread on even steps s<16
            // (8 copies/thread/chunk total; group committed at chunk end,
            // consumed after CP_WAIT0 -> >=16 steps of latency headroom).
            if (more && s < 16 && (s & 1) == 0) {
                int m = s >> 1;                    // 0..7
                int id = i + 64 * m;
                int st = id >> 4, gp = id & 15;
                CP_ASYNC16(smem_u32(&s_xp[xbuf ^ 1][st * HDIM + gp * 4]),
                           g_proj + s_tok[(c + 1) * CHUNK + st] * HDIM + gp * 4);
            }

            const int cur = s & 1, nxt = cur ^ 1;  // CHUNK even -> parity resets
            float xp = s_xp[xbuf][s * HDIM + i];

            unsigned long long a0, a1 = 0ULL, a2 = 0ULL, a3 = 0ULL;
            asm("mov.b64 %0, {%1, %2};" : "=l"(a0) : "f"(xp), "f"(0.0f));

            const ulonglong2* hp = (const ulonglong2*)s_h[cur];
            #pragma unroll
            for (int q = 0; q < 16; q += 2) {      // 16 broadcast LDS.128
                ulonglong2 u0 = hp[q], u1 = hp[q + 1];
                FMA2(a0, u0.x, wp[2 * q + 0]);
                FMA2(a1, u0.y, wp[2 * q + 1]);
                FMA2(a2, u1.x, wp[2 * q + 2]);
                FMA2(a3, u1.y, wp[2 * q + 3]);
            }
            ADD2(a0, a1); ADD2(a2, a3); ADD2(a0, a2);

            float e, o;
            asm("mov.b64 {%0, %1}, %2;" : "=f"(e), "=f"(o) : "l"(a0));
            hv = fast_tanh(e + o);
            s_h[nxt][i] = hv;
            __syncthreads();
        }
        CP_COMMIT(); CP_WAIT0();
        __syncthreads();
    }

    // fc + sigmoid: logit = sum_i h[i]*fc_w[i] + fc_b[0]
    float v = hv * fc_w[i];
    #pragma unroll
    for (int off = 16; off; off >>= 1)
        v += __shfl_xor_sync(0xffffffff, v, off);
    if ((i & 31) == 0) s_part[i >> 5] = make_float2(v, 0.0f);
    __syncthreads();
    if (i == 0) {
        float logit = s_part[0].x + s_part[1].x + fc_b[0];
        out[row] = 1.0f / (1.0f + expf(-logit));
    }
}

// ---------------------------------------------------------------------------
// Launch. Inputs (metadata order): x, emb, W_ih, W_hh, b_ih, b_hh, fc_w, fc_b
// 2 launches/call so ncu -s 5 -c 1 lands on rnn_row_kernel.
// ---------------------------------------------------------------------------
extern "C" void kernel_launch(void* const* d_in, const int* in_sizes, int n_in,
                              void* d_out, int out_size)
{
    const int*   x32  = (const int*)  d_in[0];
    const float* emb  = (const float*)d_in[1];
    const float* W_ih = (const float*)d_in[2];
    const float* W_hh = (const float*)d_in[3];
    const float* b_ih = (const float*)d_in[4];
    const float* b_hh = (const float*)d_in[5];
    const float* fc_w = (const float*)d_in[6];
    const float* fc_b = (const float*)d_in[7];
    float* out = (float*)d_out;

    proj_kernel<<<(VOCAB + PROJ_ROWS - 1) / PROJ_ROWS, 256>>>(x32, emb, W_ih, b_ih, b_hh);
    rnn_row_kernel<<<BATCH, 64>>>(x32, W_hh, fc_w, fc_b, out);
}

// round 10
// speedup vs baseline: 1.0168x; 1.0168x over previous
#include <cuda_runtime.h>
#include <cuda_bf16.h>
#include <cstdint>

// Problem dims (fixed by the reference)
#define VOCAB 50000
#define EDIM  64
#define HDIM  64
#define BATCH 1024
#define SEQ   512

// Scratch: projected table proj[v][h] = b_ih[h]+b_hh[h] + sum_e emb[v,e]*W_ih[h,e]
__device__ float g_proj[VOCAB * HDIM];   // 12.8 MB, L2-resident in steady state
__device__ int   g_x64flag;              // 1 if token buffer is int64, 0 if int32

// Fast tanh: tanh(x) = 1 - 2/(1 + exp(2x)). ex2.approx + rcp.approx,
// rel err ~1e-6 (vs ~6e-4 for tanh.approx.f32, which would risk the 1e-3 gate).
__device__ __forceinline__ float fast_tanh(float x) {
    float e, r;
    asm("ex2.approx.f32 %0, %1;" : "=f"(e) : "f"(x * 2.885390081777927f)); // 2/ln2
    asm("rcp.approx.f32 %0, %1;" : "=f"(r) : "f"(e + 1.0f));
    return fmaf(-2.0f, r, 1.0f);
}

#define FMA2(acc, a, b) asm("fma.rn.f32x2 %0, %1, %2, %0;" : "+l"(acc) : "l"(a), "l"(b))
#define ADD2(acc, b)    asm("add.rn.f32x2 %0, %0, %1;"     : "+l"(acc) : "l"(b))
#define PACK2(d, lo, hi) asm("mov.b64 %0, {%1, %2};" : "=l"(d) : "f"(lo), "f"(hi))
#define UNPACK2(lo, hi, s) asm("mov.b64 {%0, %1}, %2;" : "=f"(lo), "=f"(hi) : "l"(s))

// ---------------------------------------------------------------------------
// Kernel A: build projected embedding table (fuses gather-side GEMM + biases).
// Block 0 warp 0 additionally detects int32-vs-int64 token layout: tokens are
// in [0,50000), so for little-endian int64 every odd 32-bit word is 0.
// ---------------------------------------------------------------------------
#define PROJ_ROWS 32
__global__ __launch_bounds__(256) void proj_kernel(
    const int*   __restrict__ x32,
    const float* __restrict__ emb,
    const float* __restrict__ W_ih,
    const float* __restrict__ b_ih,
    const float* __restrict__ b_hh)
{
    __shared__ float s_w[HDIM * 65];
    __shared__ float s_e[PROJ_ROWS * EDIM];
    __shared__ float s_bias[HDIM];

    const int t  = threadIdx.x;
    const int v0 = blockIdx.x * PROJ_ROWS;

    if (blockIdx.x == 0 && t < 32) {
        unsigned m = __ballot_sync(0xffffffff, x32[2 * t + 1] != 0);
        if (t == 0) g_x64flag = (m == 0u) ? 1 : 0;
    }

    #pragma unroll
    for (int k = 0; k < 16; k++) {
        int idx = t + k * 256;                 // 0..4095
        int hg = idx >> 6, eg = idx & 63;
        s_w[hg * 65 + eg] = W_ih[idx];
    }
    #pragma unroll
    for (int k = 0; k < 8; k++) {
        int idx = t + k * 256;                 // 0..2047
        int r = idx >> 6, e = idx & 63;
        s_e[idx] = (v0 + r < VOCAB) ? emb[(long)(v0 + r) * EDIM + e] : 0.0f;
    }
    if (t < HDIM) s_bias[t] = b_ih[t] + b_hh[t];
    __syncthreads();

    const int h    = t & 63;
    const int rgrp = t >> 6;                   // 0..3
    #pragma unroll
    for (int k = 0; k < 8; k++) {
        int r = rgrp + 4 * k;                  // 0..31
        if (v0 + r >= VOCAB) break;
        float acc = s_bias[h];
        #pragma unroll
        for (int e = 0; e < EDIM; e++)
            acc += s_e[r * EDIM + e] * s_w[h * 65 + e];
        g_proj[(v0 + r) * HDIM + h] = acc;
    }
}

// ---------------------------------------------------------------------------
// Kernel B: warp-synchronous shuffle-broadcast recurrence. One warp per row.
// Lane t owns outputs h[2t], h[2t+1] IN REGISTERS (its own tanh results);
// nothing touches shared memory in the hot loop -> the L1-return wall (72%
// in R8) is gone, and there are no barriers of any kind.
// Step: 32 rounds; round g broadcasts lane g's (h[2g], h[2g+1]) via 2 SHFL,
// then 2 FFMA2 against statically-indexed packed weight pairs.
// xp: depth-3 register pipeline of coalesced LDG.64 from g_proj (L2-hit,
// token-indexed -> no dependence on h, fully prefetchable).
// ---------------------------------------------------------------------------
__global__ __launch_bounds__(32, 6) void rnn_shfl_kernel(
    const int*   __restrict__ x32,
    const float* __restrict__ W_hh,
    const float* __restrict__ fc_w,
    const float* __restrict__ fc_b,
    float*       __restrict__ out)
{
    __shared__ int s_tok[SEQ];                 // 2 KB

    const int lane = threadIdx.x;
    const int row  = blockIdx.x;
    const int flag = g_x64flag;

    // Tokens for this row (handles int32 or int64 source layout)
    for (int k = lane; k < SEQ; k += 32) {
        long base = (long)row * SEQ + k;
        s_tok[k] = flag ? x32[2 * base] : x32[base];
    }
    __syncwarp();

    // Weights for outputs i0 = 2*lane, i1 = 2*lane+1, packed over j-pairs:
    // wp0[g] = (W[i0][2g], W[i0][2g+1]), wp1[g] likewise. 128 regs, no dup.
    unsigned long long wp0[32], wp1[32];
    {
        const ulonglong2* a = (const ulonglong2*)(W_hh + (2 * lane)     * HDIM);
        const ulonglong2* b = (const ulonglong2*)(W_hh + (2 * lane + 1) * HDIM);
        #pragma unroll
        for (int q = 0; q < 16; q++) {
            ulonglong2 u = a[q]; wp0[2 * q] = u.x; wp0[2 * q + 1] = u.y;
            ulonglong2 v = b[q]; wp1[2 * q] = v.x; wp1[2 * q + 1] = v.y;
        }
    }

    float h0 = 0.0f, h1 = 0.0f;    // h[2*lane], h[2*lane+1]

    // xp register pipeline, depth 3 (covers ~3 steps of L2 latency)
    float2 xp0 = *(const float2*)(g_proj + s_tok[0] * HDIM + 2 * lane);
    float2 xp1 = *(const float2*)(g_proj + s_tok[1] * HDIM + 2 * lane);
    float2 xp2 = *(const float2*)(g_proj + s_tok[2] * HDIM + 2 * lane);

    #pragma unroll 2
    for (int t = 0; t < SEQ; t++) {
        const int tp = (t + 3 < SEQ) ? (t + 3) : (SEQ - 1);
        float2 xpf = *(const float2*)(g_proj + s_tok[tp] * HDIM + 2 * lane);

        unsigned long long a00, a01 = 0ULL, a10, a11 = 0ULL;
        PACK2(a00, xp0.x, 0.0f);
        PACK2(a10, xp0.y, 0.0f);

        #pragma unroll
        for (int g = 0; g < 32; g += 2) {
            float b0 = __shfl_sync(0xffffffffu, h0, g);
            float b1 = __shfl_sync(0xffffffffu, h1, g);
            unsigned long long hb; PACK2(hb, b0, b1);
            FMA2(a00, hb, wp0[g]);
            FMA2(a10, hb, wp1[g]);
            float c0 = __shfl_sync(0xffffffffu, h0, g + 1);
            float c1 = __shfl_sync(0xffffffffu, h1, g + 1);
            unsigned long long hc; PACK2(hc, c0, c1);
            FMA2(a01, hc, wp0[g + 1]);
            FMA2(a11, hc, wp1[g + 1]);
        }
        ADD2(a00, a01);
        ADD2(a10, a11);

        float e0, o0, e1, o1;
        UNPACK2(e0, o0, a00);
        UNPACK2(e1, o1, a10);
        h0 = fast_tanh(e0 + o0);
        h1 = fast_tanh(e1 + o1);

        xp0 = xp1;
        xp1 = xp2;
        xp2 = xpf;
    }

    // fc + sigmoid: logit = sum_i h[i]*fc_w[i] + fc_b[0]
    float2 f = *(const float2*)(fc_w + 2 * lane);
    float v = h0 * f.x + h1 * f.y;
    #pragma unroll
    for (int off = 16; off; off >>= 1)
        v += __shfl_xor_sync(0xffffffffu, v, off);
    if (lane == 0)
        out[row] = 1.0f / (1.0f + expf(-(v + fc_b[0])));
}

// ---------------------------------------------------------------------------
// Launch. Inputs (metadata order): x, emb, W_ih, W_hh, b_ih, b_hh, fc_w, fc_b
// 2 launches/call so ncu -s 5 -c 1 lands on rnn_shfl_kernel.
// ---------------------------------------------------------------------------
extern "C" void kernel_launch(void* const* d_in, const int* in_sizes, int n_in,
                              void* d_out, int out_size)
{
    const int*   x32  = (const int*)  d_in[0];
    const float* emb  = (const float*)d_in[1];
    const float* W_ih = (const float*)d_in[2];
    const float* W_hh = (const float*)d_in[3];
    const float* b_ih = (const float*)d_in[4];
    const float* b_hh = (const float*)d_in[5];
    const float* fc_w = (const float*)d_in[6];
    const float* fc_b = (const float*)d_in[7];
    float* out = (float*)d_out;

    proj_kernel<<<(VOCAB + PROJ_ROWS - 1) / PROJ_ROWS, 256>>>(x32, emb, W_ih, b_ih, b_hh);
    rnn_shfl_kernel<<<BATCH, 32>>>(x32, W_hh, fc_w, fc_b, out);
}

// round 11
// speedup vs baseline: 1.1514x; 1.1324x over previous
#include <cuda_runtime.h>
#include <cuda_bf16.h>
#include <cstdint>

// Problem dims (fixed by the reference)
#define VOCAB 50000
#define EDIM  64
#define HDIM  64
#define BATCH 1024
#define SEQ   512

// Scratch: projected table proj[v][h] = b_ih[h]+b_hh[h] + sum_e emb[v,e]*W_ih[h,e]
__device__ float g_proj[VOCAB * HDIM];   // 12.8 MB, L2-resident in steady state
__device__ int   g_x64flag;              // 1 if token buffer is int64, 0 if int32

// Fast tanh: tanh(x) = 1 - 2/(1 + exp(2x)). ex2.approx + rcp.approx,
// rel err ~1e-6 (vs ~6e-4 for tanh.approx.f32, which would risk the 1e-3 gate).
__device__ __forceinline__ float fast_tanh(float x) {
    float e, r;
    asm("ex2.approx.f32 %0, %1;" : "=f"(e) : "f"(x * 2.885390081777927f)); // 2/ln2
    asm("rcp.approx.f32 %0, %1;" : "=f"(r) : "f"(e + 1.0f));
    return fmaf(-2.0f, r, 1.0f);
}

#define FMA2(acc, a, b) asm("fma.rn.f32x2 %0, %1, %2, %0;" : "+l"(acc) : "l"(a), "l"(b))
#define ADD2(acc, b)    asm("add.rn.f32x2 %0, %0, %1;"     : "+l"(acc) : "l"(b))
#define PACK2(d, lo, hi) asm("mov.b64 %0, {%1, %2};" : "=l"(d) : "f"(lo), "f"(hi))
#define UNPACK2(lo, hi, s) asm("mov.b64 {%0, %1}, %2;" : "=f"(lo), "=f"(hi) : "l"(s))

// ---------------------------------------------------------------------------
// Kernel A: build projected embedding table (fuses gather-side GEMM + biases).
// Block 0 warp 0 additionally detects int32-vs-int64 token layout: tokens are
// in [0,50000), so for little-endian int64 every odd 32-bit word is 0.
// ---------------------------------------------------------------------------
#define PROJ_ROWS 32
__global__ __launch_bounds__(256) void proj_kernel(
    const int*   __restrict__ x32,
    const float* __restrict__ emb,
    const float* __restrict__ W_ih,
    const float* __restrict__ b_ih,
    const float* __restrict__ b_hh)
{
    __shared__ float s_w[HDIM * 65];
    __shared__ float s_e[PROJ_ROWS * EDIM];
    __shared__ float s_bias[HDIM];

    const int t  = threadIdx.x;
    const int v0 = blockIdx.x * PROJ_ROWS;

    if (blockIdx.x == 0 && t < 32) {
        unsigned m = __ballot_sync(0xffffffff, x32[2 * t + 1] != 0);
        if (t == 0) g_x64flag = (m == 0u) ? 1 : 0;
    }

    #pragma unroll
    for (int k = 0; k < 16; k++) {
        int idx = t + k * 256;                 // 0..4095
        int hg = idx >> 6, eg = idx & 63;
        s_w[hg * 65 + eg] = W_ih[idx];
    }
    #pragma unroll
    for (int k = 0; k < 8; k++) {
        int idx = t + k * 256;                 // 0..2047
        int r = idx >> 6, e = idx & 63;
        s_e[idx] = (v0 + r < VOCAB) ? emb[(long)(v0 + r) * EDIM + e] : 0.0f;
    }
    if (t < HDIM) s_bias[t] = b_ih[t] + b_hh[t];
    __syncthreads();

    const int h    = t & 63;
    const int rgrp = t >> 6;                   // 0..3
    #pragma unroll
    for (int k = 0; k < 8; k++) {
        int r = rgrp + 4 * k;                  // 0..31
        if (v0 + r >= VOCAB) break;
        float acc = s_bias[h];
        #pragma unroll
        for (int e = 0; e < EDIM; e++)
            acc += s_e[r * EDIM + e] * s_w[h * 65 + e];
        g_proj[(v0 + r) * HDIM + h] = acc;
    }
}

// ---------------------------------------------------------------------------
// Kernel B: warp-private LDS.128 broadcast recurrence.
// Block = 128 threads = 4 warps (covers all 4 SMSPs: kills the small-block
// SMSP pileup seen in R6/R8). Each warp = one batch row, fully autonomous:
// no __syncthreads anywhere in the hot loop. Lane t owns outputs
// h[2t], h[2t+1] (weights = 128 regs, j-pair packed, direct LDG.128).
// Broadcast instrument = LDS.128 (512B / 4 MIO-cyc — measured 2x better per
// MIO cycle than SHFL): per step each lane STS.64's its own pair into the
// warp's double-buffered h line, __syncwarp, then 16 LDS.128 reads.
// xp: depth-3 register pipeline of coalesced LDG.64 from g_proj.
// ---------------------------------------------------------------------------
__global__ __launch_bounds__(128, 2) void rnn_w4_kernel(
    const int*   __restrict__ x32,
    const float* __restrict__ W_hh,
    const float* __restrict__ fc_w,
    const float* __restrict__ fc_b,
    float*       __restrict__ out)
{
    __shared__ int   s_tok[4][SEQ];            // 8 KB  [warp][t]
    __shared__ float s_h[4][2][HDIM];          // 2 KB  [warp][buf][h]

    const int w    = threadIdx.x >> 5;         // warp in block: 0..3
    const int lane = threadIdx.x & 31;
    const int row  = blockIdx.x * 4 + w;
    const int flag = g_x64flag;

    // Tokens for this warp's row (handles int32 or int64 source layout)
    for (int k = lane; k < SEQ; k += 32) {
        long base = (long)row * SEQ + k;
        s_tok[w][k] = flag ? x32[2 * base] : x32[base];
    }
    __syncwarp();

    // Weights for outputs i0 = 2*lane, i1 = 2*lane+1, packed over j-pairs:
    // wp0[g] = (W[i0][2g], W[i0][2g+1]), wp1 likewise. 128 regs, no dup.
    unsigned long long wp0[32], wp1[32];
    {
        const ulonglong2* a = (const ulonglong2*)(W_hh + (2 * lane)     * HDIM);
        const ulonglong2* b = (const ulonglong2*)(W_hh + (2 * lane + 1) * HDIM);
        #pragma unroll
        for (int q = 0; q < 16; q++) {
            ulonglong2 u = a[q]; wp0[2 * q] = u.x; wp0[2 * q + 1] = u.y;
            ulonglong2 v = b[q]; wp1[2 * q] = v.x; wp1[2 * q + 1] = v.y;
        }
    }

    // h init (buffer 0)
    *(float2*)&s_h[w][0][2 * lane] = make_float2(0.0f, 0.0f);
    __syncwarp();

    float h0 = 0.0f, h1 = 0.0f;

    // xp register pipeline, depth 3 (covers ~3 steps of L2 latency)
    float2 xp0 = *(const float2*)(g_proj + s_tok[w][0] * HDIM + 2 * lane);
    float2 xp1 = *(const float2*)(g_proj + s_tok[w][1] * HDIM + 2 * lane);
    float2 xp2 = *(const float2*)(g_proj + s_tok[w][2] * HDIM + 2 * lane);

    #pragma unroll 2
    for (int t = 0; t < SEQ; t++) {
        const int cur = t & 1, nxt = cur ^ 1;
        const int tp = (t + 3 < SEQ) ? (t + 3) : (SEQ - 1);
        float2 xpf = *(const float2*)(g_proj + s_tok[w][tp] * HDIM + 2 * lane);

        unsigned long long a00, a01 = 0ULL, a10, a11 = 0ULL;
        PACK2(a00, xp0.x, 0.0f);
        PACK2(a10, xp0.y, 0.0f);

        // 16 broadcast LDS.128 over the warp-private h line
        const ulonglong2* hp = (const ulonglong2*)s_h[w][cur];
        #pragma unroll
        for (int q = 0; q < 16; q++) {         // hp[q] = h[4q..4q+3]
            ulonglong2 u = hp[q];
            FMA2(a00, u.x, wp0[2 * q + 0]);
            FMA2(a01, u.y, wp0[2 * q + 1]);
            FMA2(a10, u.x, wp1[2 * q + 0]);
            FMA2(a11, u.y, wp1[2 * q + 1]);
        }
        ADD2(a00, a01);
        ADD2(a10, a11);

        float e0, o0, e1, o1;
        UNPACK2(e0, o0, a00);
        UNPACK2(e1, o1, a10);
        h0 = fast_tanh(e0 + o0);
        h1 = fast_tanh(e1 + o1);

        // Publish own pair for next step (other buffer), warp-local sync only
        *(float2*)&s_h[w][nxt][2 * lane] = make_float2(h0, h1);
        __syncwarp();

        xp0 = xp1;
        xp1 = xp2;
        xp2 = xpf;
    }

    // fc + sigmoid: logit = sum_i h[i]*fc_w[i] + fc_b[0]  (warp-local)
    float2 f = *(const float2*)(fc_w + 2 * lane);
    float v = h0 * f.x + h1 * f.y;
    #pragma unroll
    for (int off = 16; off; off >>= 1)
        v += __shfl_xor_sync(0xffffffffu, v, off);
    if (lane == 0)
        out[row] = 1.0f / (1.0f + expf(-(v + fc_b[0])));
}

// ---------------------------------------------------------------------------
// Launch. Inputs (metadata order): x, emb, W_ih, W_hh, b_ih, b_hh, fc_w, fc_b
// 2 launches/call so ncu -s 5 -c 1 lands on rnn_w4_kernel.
// ---------------------------------------------------------------------------
extern "C" void kernel_launch(void* const* d_in, const int* in_sizes, int n_in,
                              void* d_out, int out_size)
{
    const int*   x32  = (const int*)  d_in[0];
    const float* emb  = (const float*)d_in[1];
    const float* W_ih = (const float*)d_in[2];
    const float* W_hh = (const float*)d_in[3];
    const float* b_ih = (const float*)d_in[4];
    const float* b_hh = (const float*)d_in[5];
    const float* fc_w = (const float*)d_in[6];
    const float* fc_b = (const float*)d_in[7];
    float* out = (float*)d_out;

    proj_kernel<<<(VOCAB + PROJ_ROWS - 1) / PROJ_ROWS, 256>>>(x32, emb, W_ih, b_ih, b_hh);
    rnn_w4_kernel<<<BATCH / 4, 128>>>(x32, W_hh, fc_w, fc_b, out);
}